// round 16
// baseline (speedup 1.0000x reference)
#include <cuda_runtime.h>
#include <math.h>
#include <mma.h>
using namespace nvcuda;

#define NPIX 4096
#define NTOT (4 * NPIX)

// ---------------- scratch ----------------
__device__ float g_edge32T[4 * 128 * 1024];   // conv out, c-major [b][c][p32]
__device__ float g_fused32T[4 * 128 * 1024];  // conv out, c-major
__device__ float g_xq[4 * 128 * NPIX];        // raw upsampled edge, c-major
__device__ float g_fusedT[4 * 128 * NPIX];    // c-major
__device__ float g_xk[4 * 128 * NPIX];        // sem*density, c-major
__device__ float g_v[NTOT * 256];             // sem_val px-major [bp][c]
__device__ float g_l2e[NTOT];
__device__ float g_sim[NTOT];
__device__ float g_dens[NTOT];
__device__ float g_q[NTOT * 256];             // [bp][o]
__device__ float g_k[NTOT * 256];             // [bp][o]
__device__ float g_aoT[4 * 256 * NPIX];       // attention out, c-major
__device__ float g_wqT[128 * 256];
__device__ float g_wkT[256 * 256];
__device__ float g_wfT[256 * 128];
__device__ float g_waT[64 * 128];             // align conv weight, [c][o]
__device__ float g_wfaT[128 * 128];           // fused-align conv weight, [c][o]

__device__ __forceinline__ void cp16(void* dst, const void* src) {
    unsigned d = (unsigned)__cvta_generic_to_shared(dst);
    asm volatile("cp.async.cg.shared.global [%0], [%1], 16;" ::"r"(d), "l"(src) : "memory");
}
__device__ __forceinline__ void cp_commit() {
    asm volatile("cp.async.commit_group;" ::: "memory");
}
template <int N>
__device__ __forceinline__ void cp_wait() {
    asm volatile("cp.async.wait_group %0;" ::"n"(N) : "memory");
}

// ---------------- K0: all weight transposes (+fold Q concat) ----------------
__global__ void wprep_kernel(const float* __restrict__ wq, const float* __restrict__ wk,
                             const float* __restrict__ wf, const float* __restrict__ wa,
                             const float* __restrict__ wfa) {
    int i = blockIdx.x * 256 + threadIdx.x;   // 155648 total
    if (i < 32768) {
        int c = i >> 8, o = i & 255;
        g_wqT[i] = wq[o * 256 + c] + wq[o * 256 + c + 128];
    } else if (i < 98304) {
        int j = i - 32768;
        int c = j >> 8, o = j & 255;
        g_wkT[j] = wk[o * 256 + c];
    } else if (i < 131072) {
        int j = i - 98304;
        int c = j >> 7, o = j & 127;
        g_wfT[j] = wf[o * 256 + c];
    } else if (i < 139264) {
        int j = i - 131072;
        int c = j >> 7, o = j & 127;
        g_waT[j] = wa[o * 64 + c];
    } else if (i < 155648) {
        int j = i - 139264;
        int c = j >> 7, o = j & 127;
        g_wfaT[j] = wfa[o * 128 + c];
    }
}

// ---------------- K1: prep, thread = pixel (fully coalesced) ----------------
__global__ void prep_kernel(const float* __restrict__ sem) {
    int t = threadIdx.x;
    int px = t & 63, cg = t >> 6;
    int bp = blockIdx.x * 64 + px;
    int b = bp >> 12, p = bp & 4095;
    int oy = p >> 6, ox = p & 63;

    float sy = oy * 0.5f - 0.25f;
    int y0i = (int)floorf(sy);
    float wy = sy - (float)y0i;
    int y0 = y0i < 0 ? 0 : y0i;
    int y1 = (y0i + 1) > 31 ? 31 : (y0i + 1);
    float sx = ox * 0.5f - 0.25f;
    int x0i = (int)floorf(sx);
    float wx = sx - (float)x0i;
    int x0 = x0i < 0 ? 0 : x0i;
    int x1 = (x0i + 1) > 31 ? 31 : (x0i + 1);

    int i00 = y0 * 32 + x0, i01 = y0 * 32 + x1, i10 = y1 * 32 + x0, i11 = y1 * 32 + x1;
    float w00 = (1.f - wy) * (1.f - wx), w01 = (1.f - wy) * wx;
    float w10 = wy * (1.f - wx), w11 = wy * wx;

    const float* e32 = g_edge32T + (b << 17);
    const float* f32 = g_fused32T + (b << 17);
    const float* semb = sem + ((size_t)b << 19);

    float a = 0.f, d = 0.f, s2 = 0.f;
#pragma unroll 4
    for (int c = cg * 32; c < cg * 32 + 32; c++) {
        const float* ec = e32 + (c << 10);
        const float* fc = f32 + (c << 10);
        float ev = w00 * ec[i00] + w01 * ec[i01] + w10 * ec[i10] + w11 * ec[i11];
        float fv = w00 * fc[i00] + w01 * fc[i01] + w10 * fc[i10] + w11 * fc[i11];
        float sv = semb[((size_t)c << 12) + p];
        a += ev * ev;
        d += ev * sv;
        s2 += sv * sv;
        size_t idx = (((size_t)(b * 128 + c)) << 12) + p;
        g_xq[idx] = ev;
        g_fusedT[idx] = fv;
    }
    __shared__ float ra[4][64], rd[4][64], rs[4][64];
    ra[cg][px] = a; rd[cg][px] = d; rs[cg][px] = s2;
    __syncthreads();
    if (cg == 0) {
        a = ra[0][px] + ra[1][px] + ra[2][px] + ra[3][px];
        d = rd[0][px] + rd[1][px] + rd[2][px] + rd[3][px];
        s2 = rs[0][px] + rs[1][px] + rs[2][px] + rs[3][px];
        float l2e = sqrtf(a), l2s = sqrtf(s2);
        float sim = (d / ((l2e + 1e-6f) * (l2s + 1e-6f)) + 1.f) * 0.5f;
        g_l2e[bp] = l2e;
        g_sim[bp] = sim;
    }
}

// ---------------- K2: vbuild — transpose [sem; fused] c-major -> g_v px-major ----------------
__global__ void vbuild_kernel(const float* __restrict__ sem) {
    __shared__ float tile[32][33];
    int b = blockIdx.z;
    int p0 = blockIdx.x * 32, c0 = blockIdx.y * 32;
    int tx = threadIdx.x & 31, ty = threadIdx.x >> 5;   // 256 threads
#pragma unroll
    for (int r = 0; r < 32; r += 8) {
        int c = c0 + ty + r;
        const float* src = (c < 128) ? sem + (((size_t)(b * 128 + c)) << 12)
                                     : g_fusedT + (((size_t)(b * 128 + c - 128)) << 12);
        tile[ty + r][tx] = src[p0 + tx];
    }
    __syncthreads();
#pragma unroll
    for (int r = 0; r < 32; r += 8)
        g_v[(((size_t)(b << 12)) + p0 + ty + r) * 256 + c0 + tx] = tile[tx][ty + r];
}

// ---------------- K3: density softmax ----------------
__global__ void density_kernel() {
    __shared__ float red[32];
    __shared__ float red2[32];
    __shared__ float bmax, bsum;
    int b = blockIdx.x, t = threadIdx.x;
    float v[4];
    float mx = -1e30f;
#pragma unroll
    for (int i = 0; i < 4; i++) { v[i] = g_l2e[b * 4096 + t + i * 1024]; mx = fmaxf(mx, v[i]); }
#pragma unroll
    for (int d = 16; d; d >>= 1) mx = fmaxf(mx, __shfl_xor_sync(~0u, mx, d));
    if ((t & 31) == 0) red[t >> 5] = mx;
    __syncthreads();
    if (t < 32) {
        float m2 = red[t];
#pragma unroll
        for (int d = 16; d; d >>= 1) m2 = fmaxf(m2, __shfl_xor_sync(~0u, m2, d));
        if (t == 0) bmax = m2;
    }
    __syncthreads();
    float m = bmax;
    float s = 0.f;
#pragma unroll
    for (int i = 0; i < 4; i++) { v[i] = expf(v[i] - m); s += v[i]; }
#pragma unroll
    for (int d = 16; d; d >>= 1) s += __shfl_xor_sync(~0u, s, d);
    if ((t & 31) == 0) red2[t >> 5] = s;
    __syncthreads();
    if (t < 32) {
        float s2 = red2[t];
#pragma unroll
        for (int d = 16; d; d >>= 1) s2 += __shfl_xor_sync(~0u, s2, d);
        if (t == 0) bsum = s2;
    }
    __syncthreads();
    float f = 4096.f / bsum;
#pragma unroll
    for (int i = 0; i < 4; i++) g_dens[b * 4096 + t + i * 1024] = v[i] * f;
}

// ---------------- K4: g_xk = sem * density ----------------
__global__ void scale_kernel(const float* __restrict__ sem) {
    int i = blockIdx.x * 256 + threadIdx.x;
    int p4 = i & 1023;
    int b = i >> 17;
    float4 s = ((const float4*)sem)[i];
    float4 d = ((const float4*)(g_dens + (b << 12)))[p4];
    ((float4*)g_xk)[i] = make_float4(s.x * d.x, s.y * d.y, s.z * d.z, s.w * d.w);
}

// ---------------- TF32 tensor-core GEMM ----------------
// mode 0: Q (K=128, X=g_xq; epilogue *sim+bias)   mode 1: K (K=256)
// mode 2: F (K=256 -> out o-major, ldm 4096)
// mode 3: edge conv  (K=64,  X=ef, out=g_edge32T, ldm 1024)
// mode 4: fused conv (K=128, X=ff, out=g_fused32T, ldm 1024)
__global__ void gemm_tc_kernel(int mode, const float* __restrict__ bias, float* __restrict__ outp,
                               const float* __restrict__ xef, const float* __restrict__ xff) {
    __shared__ float Xs[2][8][132];
    __shared__ float Ws[2][8][132];
    __shared__ __align__(16) float Bs[20][132];
    int t = threadIdx.x;
    int b = blockIdx.z;
    int px0 = blockIdx.x * 128;
    int o0 = blockIdx.y * 128;
    int kkS = t >> 5;
    int f4S = (t & 31) << 2;
    int warp = t >> 5;
    int lane = t & 31;
    int wpx = (warp & 3) * 32;
    int wo = (warp >> 2) * 64;

    int Kdim = (mode == 0) ? 128 : (mode == 3) ? 64 : (mode == 4) ? 128 : 256;
    int OW = (mode <= 1) ? 256 : 128;
    const float* W = (mode == 0) ? g_wqT : (mode == 1) ? g_wkT : (mode == 2) ? g_wfT
                     : (mode == 3) ? g_waT : g_wfaT;

    auto xrow = [&](int c) -> const float* {
        if (mode == 3) return xef + (((size_t)(b * 64 + c)) << 10);
        if (mode == 4) return xff + (((size_t)(b * 128 + c)) << 10);
        if (mode == 2) return g_aoT + (((size_t)(b << 8) + c) << 12);
        if (mode == 1 && c >= 128) return g_fusedT + (((size_t)(b << 7) + (c - 128)) << 12);
        const float* base = (mode == 0) ? g_xq : g_xk;
        return base + (((size_t)(b << 7) + c) << 12);
    };
    auto stage = [&](int k0, int buf) {
        cp16(&Xs[buf][kkS][f4S], xrow(k0 + kkS) + px0 + f4S);
        cp16(&Ws[buf][kkS][f4S], W + (k0 + kkS) * OW + o0 + f4S);
        cp_commit();
    };

    if (mode != 0)
        for (int i = t; i < 2048; i += 256) Bs[i >> 7][i & 127] = bias[o0 + (i & 127)];

    stage(0, 0);
    __syncthreads();

    wmma::fragment<wmma::accumulator, 16, 16, 8, float> acc[2][4];
#pragma unroll
    for (int i = 0; i < 2; i++)
#pragma unroll
        for (int j = 0; j < 4; j++) {
            if (mode == 0) wmma::fill_fragment(acc[i][j], 0.f);
            else wmma::load_matrix_sync(acc[i][j], &Bs[0][wo + j * 16], 132, wmma::mem_row_major);
        }

    int nk = Kdim >> 3;
    for (int s = 0; s < nk; s++) {
        int buf = s & 1;
        if (s + 1 < nk) { stage((s + 1) << 3, buf ^ 1); cp_wait<1>(); }
        else cp_wait<0>();
        __syncthreads();

        wmma::fragment<wmma::matrix_a, 16, 16, 8, wmma::precision::tf32, wmma::col_major> af[2];
        wmma::fragment<wmma::matrix_b, 16, 16, 8, wmma::precision::tf32, wmma::row_major> bf[4];
#pragma unroll
        for (int i = 0; i < 2; i++) {
            wmma::load_matrix_sync(af[i], &Xs[buf][0][wpx + i * 16], 132);
#pragma unroll
            for (int e = 0; e < af[i].num_elements; e++) af[i].x[e] = wmma::__float_to_tf32(af[i].x[e]);
        }
#pragma unroll
        for (int j = 0; j < 4; j++) {
            wmma::load_matrix_sync(bf[j], &Ws[buf][0][wo + j * 16], 132);
#pragma unroll
            for (int e = 0; e < bf[j].num_elements; e++) bf[j].x[e] = wmma::__float_to_tf32(bf[j].x[e]);
        }
#pragma unroll
        for (int i = 0; i < 2; i++)
#pragma unroll
            for (int j = 0; j < 4; j++)
                wmma::mma_sync(acc[i][j], af[i], bf[j], acc[i][j]);
        __syncthreads();
    }

    if (mode == 0) {
        float* stg = &Bs[0][0] + warp * 320;   // 16x20 per-warp staging (ldm 20)
#pragma unroll
        for (int i = 0; i < 2; i++)
#pragma unroll
            for (int j = 0; j < 4; j++) {
                wmma::store_matrix_sync(stg, acc[i][j], 20, wmma::mem_row_major);
                __syncwarp();
#pragma unroll
                for (int e = lane; e < 256; e += 32) {
                    int r = e >> 4, cc = e & 15;
                    int px = px0 + wpx + i * 16 + r;
                    int o = o0 + wo + j * 16 + cc;
                    g_q[(((size_t)(b << 12) + px) << 8) + o] =
                        stg[r * 20 + cc] * g_sim[(b << 12) + px] + bias[o];
                }
                __syncwarp();
            }
    } else if (mode == 1) {
#pragma unroll
        for (int i = 0; i < 2; i++)
#pragma unroll
            for (int j = 0; j < 4; j++) {
                float* p = g_k + (((size_t)(b << 12) + px0 + wpx + i * 16) << 8) + o0 + wo + j * 16;
                wmma::store_matrix_sync(p, acc[i][j], 256, wmma::mem_row_major);
            }
    } else if (mode == 2) {
#pragma unroll
        for (int i = 0; i < 2; i++)
#pragma unroll
            for (int j = 0; j < 4; j++) {
                float* p = outp + (((size_t)(b << 7) + o0 + wo + j * 16) << 12) + px0 + wpx + i * 16;
                wmma::store_matrix_sync(p, acc[i][j], 4096, wmma::mem_col_major);
            }
    } else {
        float* dst = (mode == 3) ? g_edge32T : g_fused32T;
#pragma unroll
        for (int i = 0; i < 2; i++)
#pragma unroll
            for (int j = 0; j < 4; j++) {
                float* p = dst + (((size_t)((b << 7) + o0 + wo + j * 16)) << 10) + px0 + wpx + i * 16;
                wmma::store_matrix_sync(p, acc[i][j], 1024, wmma::mem_col_major);
            }
    }
}

// ---------------- K6: windowed attention — tf32 wmma QK+AV, V via cp.async from g_v ----
#define KVS 40
#define ATTN_SMEM ((32 * 256 + 256 * KVS + 4 * 32 * KVS) * 4 + 2048)

__global__ void __launch_bounds__(512, 2) attn_kernel() {
    extern __shared__ float sm[];
    float* q_s = sm;                  // 32x256 (Q during QK; P after)
    float* Ssm = sm;                  // alias
    float* kv = sm + 32 * 256;        // 256 x KVS
    float* outp = kv + 256 * KVS;     // 4 x (32 x KVS)
    int* mky = (int*)(outp + 4 * 32 * KVS);
    int* mkx = mky + 256;

    int t = threadIdx.x;
    int warp = t >> 5;
    int blk = blockIdx.x;
    int b = blk >> 7;
    int tile = blk & 127;
    int qy0 = (tile >> 4) * 8, qx0 = (tile & 15) * 4;
    int uy0 = qy0 - 5 < 0 ? 0 : qy0 - 5;
    int uy1 = qy0 + 12 > 63 ? 63 : qy0 + 12;
    int ux0 = qx0 - 5 < 0 ? 0 : qx0 - 5;
    int ux1 = qx0 + 8 > 63 ? 63 : qx0 + 8;
    int uw = ux1 - ux0 + 1;
    int M = (uy1 - uy0 + 1) * uw;

    if (t < 256) {
        int ry = t / uw;
        mky[t] = uy0 + ry;
        mkx[t] = ux0 + (t - ry * uw);
    }
    __syncthreads();

    // stage Q (32 x 256)
    for (int i = t; i < 2048; i += 512) {
        int qi = i >> 6, f4 = (i & 63) << 2;
        int qy = qy0 + (qi >> 2), qx = qx0 + (qi & 3);
        cp16(q_s + qi * 256 + f4, g_q + ((((b << 12) + (qy << 6) + qx) << 8) + f4));
    }
    cp_commit();

    // ---- QK via wmma ----
    wmma::fragment<wmma::accumulator, 16, 16, 8, float> sacc[2];
    wmma::fill_fragment(sacc[0], 0.f);
    wmma::fill_fragment(sacc[1], 0.f);
    int mt = warp & 1, nt0 = warp >> 1;

    for (int ch = 0; ch < 8; ch++) {
        __syncthreads();
        for (int i = t; i < 2048; i += 512) {
            int r = i >> 3, f4 = (i & 7) << 2;
            if (r < M) {
                int m = (mky[r] << 6) + mkx[r];
                cp16(kv + r * KVS + f4, g_k + ((((b << 12) + m) << 8) + (ch << 5) + f4));
            } else {
                *(float4*)(kv + r * KVS + f4) = make_float4(0.f, 0.f, 0.f, 0.f);
            }
        }
        cp_commit();
        cp_wait<0>();
        __syncthreads();
#pragma unroll
        for (int s = 0; s < 4; s++) {
            wmma::fragment<wmma::matrix_a, 16, 16, 8, wmma::precision::tf32, wmma::row_major> af;
            wmma::fragment<wmma::matrix_b, 16, 16, 8, wmma::precision::tf32, wmma::col_major> bf0, bf1;
            wmma::load_matrix_sync(af, &q_s[mt * 16 * 256 + (ch << 5) + s * 8], 256);
#pragma unroll
            for (int e = 0; e < af.num_elements; e++) af.x[e] = wmma::__float_to_tf32(af.x[e]);
            wmma::load_matrix_sync(bf0, &kv[nt0 * 16 * KVS + s * 8], KVS);
            wmma::load_matrix_sync(bf1, &kv[(nt0 + 8) * 16 * KVS + s * 8], KVS);
#pragma unroll
            for (int e = 0; e < bf0.num_elements; e++) {
                bf0.x[e] = wmma::__float_to_tf32(bf0.x[e]);
                bf1.x[e] = wmma::__float_to_tf32(bf1.x[e]);
            }
            wmma::mma_sync(sacc[0], af, bf0, sacc[0]);
            wmma::mma_sync(sacc[1], af, bf1, sacc[1]);
        }
    }
    __syncthreads();
    wmma::store_matrix_sync(&Ssm[mt * 16 * 256 + nt0 * 16], sacc[0], 256, wmma::mem_row_major);
    wmma::store_matrix_sync(&Ssm[mt * 16 * 256 + (nt0 + 8) * 16], sacc[1], 256, wmma::mem_row_major);
    __syncthreads();

    // ---- mask + softmax (fp32 exact) ----
    {
        int qi = t >> 4, l = t & 15;
        int qy = qy0 + (qi >> 2), qx = qx0 + (qi & 3);
        float v[16];
        float mx = -1e30f;
#pragma unroll
        for (int k = 0; k < 16; k++) {
            int s = l + 16 * k;
            float raw = Ssm[qi * 256 + s];
            int dy = mky[s] - qy; if (dy < 0) dy = -dy;
            int dx = mkx[s] - qx; if (dx < 0) dx = -dx;
            v[k] = (s < M && dy <= 5 && dx <= 5) ? raw * 0.0625f : -1e30f;
            mx = fmaxf(mx, v[k]);
        }
#pragma unroll
        for (int d = 8; d; d >>= 1) mx = fmaxf(mx, __shfl_xor_sync(~0u, mx, d));
        float s = 0.f;
#pragma unroll
        for (int k = 0; k < 16; k++) { v[k] = expf(v[k] - mx); s += v[k]; }
#pragma unroll
        for (int d = 8; d; d >>= 1) s += __shfl_xor_sync(~0u, s, d);
        float inv = 1.f / s;
#pragma unroll
        for (int k = 0; k < 16; k++) Ssm[qi * 256 + l + 16 * k] = v[k] * inv;
    }

    // ---- AV via wmma; V staged from g_v (row-major, cp.async) ----
    int kq = warp >> 2;
    int mtv = (warp >> 1) & 1;
    int ntc = warp & 1;

    for (int ch = 0; ch < 8; ch++) {
        __syncthreads();
        for (int i = t; i < 2048; i += 512) {
            int r = i >> 3, f4 = (i & 7) << 2;
            if (r < M) {
                int m = (mky[r] << 6) + mkx[r];
                cp16(kv + r * KVS + f4, g_v + ((((size_t)(b << 12) + m) << 8) + (ch << 5) + f4));
            } else {
                *(float4*)(kv + r * KVS + f4) = make_float4(0.f, 0.f, 0.f, 0.f);
            }
        }
        cp_commit();
        cp_wait<0>();
        __syncthreads();

        wmma::fragment<wmma::accumulator, 16, 16, 8, float> oacc;
        wmma::fill_fragment(oacc, 0.f);
#pragma unroll
        for (int s = 0; s < 8; s++) {
            wmma::fragment<wmma::matrix_a, 16, 16, 8, wmma::precision::tf32, wmma::row_major> pf;
            wmma::fragment<wmma::matrix_b, 16, 16, 8, wmma::precision::tf32, wmma::row_major> vf;
            wmma::load_matrix_sync(pf, &Ssm[mtv * 16 * 256 + kq * 64 + s * 8], 256);
            wmma::load_matrix_sync(vf, &kv[(kq * 64 + s * 8) * KVS + ntc * 16], KVS);
#pragma unroll
            for (int e = 0; e < pf.num_elements; e++) pf.x[e] = wmma::__float_to_tf32(pf.x[e]);
#pragma unroll
            for (int e = 0; e < vf.num_elements; e++) vf.x[e] = wmma::__float_to_tf32(vf.x[e]);
            wmma::mma_sync(oacc, pf, vf, oacc);
        }
        wmma::store_matrix_sync(&outp[kq * 32 * KVS + mtv * 16 * KVS + ntc * 16], oacc, KVS,
                                wmma::mem_row_major);
        __syncthreads();

        for (int i = t; i < 1024; i += 512) {
            int q = i >> 5, c = i & 31;
            float vs = outp[q * KVS + c] + outp[32 * KVS + q * KVS + c] +
                       outp[64 * KVS + q * KVS + c] + outp[96 * KVS + q * KVS + c];
            int pix = ((qy0 + (q >> 2)) << 6) + qx0 + (q & 3);
            g_aoT[(((size_t)(b << 8) + (ch << 5) + c) << 12) + pix] = vs;
        }
    }
}

// ---------------- launch ----------------
extern "C" void kernel_launch(void* const* d_in, const int* in_sizes, int n_in,
                              void* d_out, int out_size) {
    const float* ef  = (const float*)d_in[0];
    const float* sem = (const float*)d_in[1];
    const float* ff  = (const float*)d_in[2];
    const float* wa  = (const float*)d_in[3];
    const float* ba  = (const float*)d_in[4];
    const float* wfa = (const float*)d_in[5];
    const float* bfa = (const float*)d_in[6];
    const float* wq  = (const float*)d_in[7];
    const float* bq  = (const float*)d_in[8];
    const float* wk  = (const float*)d_in[9];
    const float* bk  = (const float*)d_in[10];
    const float* wfu = (const float*)d_in[11];
    const float* bfu = (const float*)d_in[12];
    float* out = (float*)d_out;

    cudaFuncSetAttribute(attn_kernel, cudaFuncAttributeMaxDynamicSharedMemorySize, ATTN_SMEM);

    wprep_kernel<<<608, 256>>>(wq, wk, wfu, wa, wfa);                        // 0
    gemm_tc_kernel<<<dim3(8, 1, 4), 256>>>(3, ba, nullptr, ef, ff);          // 1 edge conv
    gemm_tc_kernel<<<dim3(8, 1, 4), 256>>>(4, bfa, nullptr, ef, ff);         // 2 fused conv
    prep_kernel<<<256, 256>>>(sem);                                          // 3 <- profiled
    density_kernel<<<4, 1024>>>();                                           // 4
    scale_kernel<<<2048, 256>>>(sem);                                        // 5
    vbuild_kernel<<<dim3(128, 8, 4), 256>>>(sem);                            // 6
    gemm_tc_kernel<<<dim3(32, 2, 4), 256>>>(0, bq, nullptr, ef, ff);         // 7 Q
    gemm_tc_kernel<<<dim3(32, 2, 4), 256>>>(1, bk, nullptr, ef, ff);         // 8 K
    attn_kernel<<<512, 512, ATTN_SMEM>>>();                                  // 9
    gemm_tc_kernel<<<dim3(32, 1, 4), 256>>>(2, bfu, out, ef, ff);            // 10 F
}

// round 17
// speedup vs baseline: 1.1821x; 1.1821x over previous
#include <cuda_runtime.h>
#include <math.h>
#include <mma.h>
using namespace nvcuda;

#define NPIX 4096
#define NTOT (4 * NPIX)

// ---------------- scratch ----------------
__device__ float g_edge32T[4 * 128 * 1024];   // conv out, c-major [b][c][p32]
__device__ float g_fused32T[4 * 128 * 1024];  // conv out, c-major
__device__ float g_xq[4 * 128 * NPIX];        // raw upsampled edge, c-major
__device__ float g_fusedT[4 * 128 * NPIX];    // c-major
__device__ float g_xk[4 * 128 * NPIX];        // sem*density, c-major
__device__ float g_v[NTOT * 256];             // sem_val px-major [bp][c]
__device__ float g_l2e[NTOT];
__device__ float g_sim[NTOT];
__device__ float g_dens[NTOT];
__device__ float g_q[NTOT * 256];             // [bp][o]
__device__ float g_k[NTOT * 256];             // [bp][o]
__device__ float g_aoT[4 * 256 * NPIX];       // attention out, c-major
__device__ float g_wqT[128 * 256];
__device__ float g_wkT[256 * 256];
__device__ float g_wfT[256 * 128];
__device__ float g_waT[64 * 128];             // align conv weight, [c][o]
__device__ float g_wfaT[128 * 128];           // fused-align conv weight, [c][o]

__device__ __forceinline__ void cp16(void* dst, const void* src) {
    unsigned d = (unsigned)__cvta_generic_to_shared(dst);
    asm volatile("cp.async.cg.shared.global [%0], [%1], 16;" ::"r"(d), "l"(src) : "memory");
}
__device__ __forceinline__ void cp_commit() {
    asm volatile("cp.async.commit_group;" ::: "memory");
}
template <int N>
__device__ __forceinline__ void cp_wait() {
    asm volatile("cp.async.wait_group %0;" ::"n"(N) : "memory");
}

// ---------------- K0: all weight transposes (+fold Q concat) ----------------
__global__ void wprep_kernel(const float* __restrict__ wq, const float* __restrict__ wk,
                             const float* __restrict__ wf, const float* __restrict__ wa,
                             const float* __restrict__ wfa) {
    int i = blockIdx.x * 256 + threadIdx.x;   // 155648 total
    if (i < 32768) {
        int c = i >> 8, o = i & 255;
        g_wqT[i] = wq[o * 256 + c] + wq[o * 256 + c + 128];
    } else if (i < 98304) {
        int j = i - 32768;
        int c = j >> 8, o = j & 255;
        g_wkT[j] = wk[o * 256 + c];
    } else if (i < 131072) {
        int j = i - 98304;
        int c = j >> 7, o = j & 127;
        g_wfT[j] = wf[o * 256 + c];
    } else if (i < 139264) {
        int j = i - 131072;
        int c = j >> 7, o = j & 127;
        g_waT[j] = wa[o * 64 + c];
    } else if (i < 155648) {
        int j = i - 139264;
        int c = j >> 7, o = j & 127;
        g_wfaT[j] = wfa[o * 128 + c];
    }
}

// ---------------- K1: prep, thread = pixel (fully coalesced) ----------------
__global__ void prep_kernel(const float* __restrict__ sem) {
    int t = threadIdx.x;
    int px = t & 63, cg = t >> 6;
    int bp = blockIdx.x * 64 + px;
    int b = bp >> 12, p = bp & 4095;
    int oy = p >> 6, ox = p & 63;

    float sy = oy * 0.5f - 0.25f;
    int y0i = (int)floorf(sy);
    float wy = sy - (float)y0i;
    int y0 = y0i < 0 ? 0 : y0i;
    int y1 = (y0i + 1) > 31 ? 31 : (y0i + 1);
    float sx = ox * 0.5f - 0.25f;
    int x0i = (int)floorf(sx);
    float wx = sx - (float)x0i;
    int x0 = x0i < 0 ? 0 : x0i;
    int x1 = (x0i + 1) > 31 ? 31 : (x0i + 1);

    int i00 = y0 * 32 + x0, i01 = y0 * 32 + x1, i10 = y1 * 32 + x0, i11 = y1 * 32 + x1;
    float w00 = (1.f - wy) * (1.f - wx), w01 = (1.f - wy) * wx;
    float w10 = wy * (1.f - wx), w11 = wy * wx;

    const float* e32 = g_edge32T + (b << 17);
    const float* f32 = g_fused32T + (b << 17);
    const float* semb = sem + ((size_t)b << 19);

    float a = 0.f, d = 0.f, s2 = 0.f;
#pragma unroll 4
    for (int c = cg * 32; c < cg * 32 + 32; c++) {
        const float* ec = e32 + (c << 10);
        const float* fc = f32 + (c << 10);
        float ev = w00 * ec[i00] + w01 * ec[i01] + w10 * ec[i10] + w11 * ec[i11];
        float fv = w00 * fc[i00] + w01 * fc[i01] + w10 * fc[i10] + w11 * fc[i11];
        float sv = semb[((size_t)c << 12) + p];
        a += ev * ev;
        d += ev * sv;
        s2 += sv * sv;
        size_t idx = (((size_t)(b * 128 + c)) << 12) + p;
        g_xq[idx] = ev;
        g_fusedT[idx] = fv;
    }
    __shared__ float ra[4][64], rd[4][64], rs[4][64];
    ra[cg][px] = a; rd[cg][px] = d; rs[cg][px] = s2;
    __syncthreads();
    if (cg == 0) {
        a = ra[0][px] + ra[1][px] + ra[2][px] + ra[3][px];
        d = rd[0][px] + rd[1][px] + rd[2][px] + rd[3][px];
        s2 = rs[0][px] + rs[1][px] + rs[2][px] + rs[3][px];
        float l2e = sqrtf(a), l2s = sqrtf(s2);
        float sim = (d / ((l2e + 1e-6f) * (l2s + 1e-6f)) + 1.f) * 0.5f;
        g_l2e[bp] = l2e;
        g_sim[bp] = sim;
    }
}

// ---------------- K2: vbuild — transpose [sem; fused] c-major -> g_v px-major ----------------
__global__ void vbuild_kernel(const float* __restrict__ sem) {
    __shared__ float tile[32][33];
    int b = blockIdx.z;
    int p0 = blockIdx.x * 32, c0 = blockIdx.y * 32;
    int tx = threadIdx.x & 31, ty = threadIdx.x >> 5;   // 256 threads
#pragma unroll
    for (int r = 0; r < 32; r += 8) {
        int c = c0 + ty + r;
        const float* src = (c < 128) ? sem + (((size_t)(b * 128 + c)) << 12)
                                     : g_fusedT + (((size_t)(b * 128 + c - 128)) << 12);
        tile[ty + r][tx] = src[p0 + tx];
    }
    __syncthreads();
#pragma unroll
    for (int r = 0; r < 32; r += 8)
        g_v[(((size_t)(b << 12)) + p0 + ty + r) * 256 + c0 + tx] = tile[tx][ty + r];
}

// ---------------- K3: density softmax ----------------
__global__ void density_kernel() {
    __shared__ float red[32];
    __shared__ float red2[32];
    __shared__ float bmax, bsum;
    int b = blockIdx.x, t = threadIdx.x;
    float v[4];
    float mx = -1e30f;
#pragma unroll
    for (int i = 0; i < 4; i++) { v[i] = g_l2e[b * 4096 + t + i * 1024]; mx = fmaxf(mx, v[i]); }
#pragma unroll
    for (int d = 16; d; d >>= 1) mx = fmaxf(mx, __shfl_xor_sync(~0u, mx, d));
    if ((t & 31) == 0) red[t >> 5] = mx;
    __syncthreads();
    if (t < 32) {
        float m2 = red[t];
#pragma unroll
        for (int d = 16; d; d >>= 1) m2 = fmaxf(m2, __shfl_xor_sync(~0u, m2, d));
        if (t == 0) bmax = m2;
    }
    __syncthreads();
    float m = bmax;
    float s = 0.f;
#pragma unroll
    for (int i = 0; i < 4; i++) { v[i] = expf(v[i] - m); s += v[i]; }
#pragma unroll
    for (int d = 16; d; d >>= 1) s += __shfl_xor_sync(~0u, s, d);
    if ((t & 31) == 0) red2[t >> 5] = s;
    __syncthreads();
    if (t < 32) {
        float s2 = red2[t];
#pragma unroll
        for (int d = 16; d; d >>= 1) s2 += __shfl_xor_sync(~0u, s2, d);
        if (t == 0) bsum = s2;
    }
    __syncthreads();
    float f = 4096.f / bsum;
#pragma unroll
    for (int i = 0; i < 4; i++) g_dens[b * 4096 + t + i * 1024] = v[i] * f;
}

// ---------------- K4: g_xk = sem * density ----------------
__global__ void scale_kernel(const float* __restrict__ sem) {
    int i = blockIdx.x * 256 + threadIdx.x;
    int p4 = i & 1023;
    int b = i >> 17;
    float4 s = ((const float4*)sem)[i];
    float4 d = ((const float4*)(g_dens + (b << 12)))[p4];
    ((float4*)g_xk)[i] = make_float4(s.x * d.x, s.y * d.y, s.z * d.z, s.w * d.w);
}

// ---------------- TF32 tensor-core GEMM ----------------
// mode 0: Q (K=128, X=g_xq; epilogue *sim+bias)   mode 1: K (K=256)
// mode 2: F (K=256 -> out o-major, ldm 4096)
// mode 3: edge conv (K=64, out=g_edge32T)  mode 4: fused conv (K=128, out=g_fused32T)
__global__ void gemm_tc_kernel(int mode, const float* __restrict__ bias, float* __restrict__ outp,
                               const float* __restrict__ xef, const float* __restrict__ xff) {
    __shared__ float Xs[2][8][132];
    __shared__ float Ws[2][8][132];
    __shared__ __align__(16) float Bs[20][132];
    int t = threadIdx.x;
    int b = blockIdx.z;
    int px0 = blockIdx.x * 128;
    int o0 = blockIdx.y * 128;
    int kkS = t >> 5;
    int f4S = (t & 31) << 2;
    int warp = t >> 5;
    int lane = t & 31;
    int wpx = (warp & 3) * 32;
    int wo = (warp >> 2) * 64;

    int Kdim = (mode == 0) ? 128 : (mode == 3) ? 64 : (mode == 4) ? 128 : 256;
    int OW = (mode <= 1) ? 256 : 128;
    const float* W = (mode == 0) ? g_wqT : (mode == 1) ? g_wkT : (mode == 2) ? g_wfT
                     : (mode == 3) ? g_waT : g_wfaT;

    auto xrow = [&](int c) -> const float* {
        if (mode == 3) return xef + (((size_t)(b * 64 + c)) << 10);
        if (mode == 4) return xff + (((size_t)(b * 128 + c)) << 10);
        if (mode == 2) return g_aoT + (((size_t)(b << 8) + c) << 12);
        if (mode == 1 && c >= 128) return g_fusedT + (((size_t)(b << 7) + (c - 128)) << 12);
        const float* base = (mode == 0) ? g_xq : g_xk;
        return base + (((size_t)(b << 7) + c) << 12);
    };
    auto stage = [&](int k0, int buf) {
        cp16(&Xs[buf][kkS][f4S], xrow(k0 + kkS) + px0 + f4S);
        cp16(&Ws[buf][kkS][f4S], W + (k0 + kkS) * OW + o0 + f4S);
        cp_commit();
    };

    if (mode != 0)
        for (int i = t; i < 2048; i += 256) Bs[i >> 7][i & 127] = bias[o0 + (i & 127)];

    stage(0, 0);
    __syncthreads();

    wmma::fragment<wmma::accumulator, 16, 16, 8, float> acc[2][4];
#pragma unroll
    for (int i = 0; i < 2; i++)
#pragma unroll
        for (int j = 0; j < 4; j++) {
            if (mode == 0) wmma::fill_fragment(acc[i][j], 0.f);
            else wmma::load_matrix_sync(acc[i][j], &Bs[0][wo + j * 16], 132, wmma::mem_row_major);
        }

    int nk = Kdim >> 3;
    for (int s = 0; s < nk; s++) {
        int buf = s & 1;
        if (s + 1 < nk) { stage((s + 1) << 3, buf ^ 1); cp_wait<1>(); }
        else cp_wait<0>();
        __syncthreads();

        wmma::fragment<wmma::matrix_a, 16, 16, 8, wmma::precision::tf32, wmma::col_major> af[2];
        wmma::fragment<wmma::matrix_b, 16, 16, 8, wmma::precision::tf32, wmma::row_major> bf[4];
#pragma unroll
        for (int i = 0; i < 2; i++) {
            wmma::load_matrix_sync(af[i], &Xs[buf][0][wpx + i * 16], 132);
#pragma unroll
            for (int e = 0; e < af[i].num_elements; e++) af[i].x[e] = wmma::__float_to_tf32(af[i].x[e]);
        }
#pragma unroll
        for (int j = 0; j < 4; j++) {
            wmma::load_matrix_sync(bf[j], &Ws[buf][0][wo + j * 16], 132);
#pragma unroll
            for (int e = 0; e < bf[j].num_elements; e++) bf[j].x[e] = wmma::__float_to_tf32(bf[j].x[e]);
        }
#pragma unroll
        for (int i = 0; i < 2; i++)
#pragma unroll
            for (int j = 0; j < 4; j++)
                wmma::mma_sync(acc[i][j], af[i], bf[j], acc[i][j]);
        __syncthreads();
    }

    if (mode == 0) {
        float* stg = &Bs[0][0] + warp * 320;   // 16x20 per-warp staging (ldm 20)
#pragma unroll
        for (int i = 0; i < 2; i++)
#pragma unroll
            for (int j = 0; j < 4; j++) {
                wmma::store_matrix_sync(stg, acc[i][j], 20, wmma::mem_row_major);
                __syncwarp();
#pragma unroll
                for (int e = lane; e < 256; e += 32) {
                    int r = e >> 4, cc = e & 15;
                    int px = px0 + wpx + i * 16 + r;
                    int o = o0 + wo + j * 16 + cc;
                    g_q[(((size_t)(b << 12) + px) << 8) + o] =
                        stg[r * 20 + cc] * g_sim[(b << 12) + px] + bias[o];
                }
                __syncwarp();
            }
    } else if (mode == 1) {
#pragma unroll
        for (int i = 0; i < 2; i++)
#pragma unroll
            for (int j = 0; j < 4; j++) {
                float* p = g_k + (((size_t)(b << 12) + px0 + wpx + i * 16) << 8) + o0 + wo + j * 16;
                wmma::store_matrix_sync(p, acc[i][j], 256, wmma::mem_row_major);
            }
    } else if (mode == 2) {
#pragma unroll
        for (int i = 0; i < 2; i++)
#pragma unroll
            for (int j = 0; j < 4; j++) {
                float* p = outp + (((size_t)(b << 7) + o0 + wo + j * 16) << 12) + px0 + wpx + i * 16;
                wmma::store_matrix_sync(p, acc[i][j], 4096, wmma::mem_col_major);
            }
    } else {
        float* dst = (mode == 3) ? g_edge32T : g_fused32T;
#pragma unroll
        for (int i = 0; i < 2; i++)
#pragma unroll
            for (int j = 0; j < 4; j++) {
                float* p = dst + (((size_t)((b << 7) + o0 + wo + j * 16)) << 10) + px0 + wpx + i * 16;
                wmma::store_matrix_sync(p, acc[i][j], 1024, wmma::mem_col_major);
            }
    }
}

// ---------------- K6: windowed attention — padded Q/S stride (bank-conflict-free) ----
#define KVS 40
#define QS 260
#define ATTN_SMEM ((32 * QS + 256 * KVS + 4 * 32 * KVS) * 4 + 2048)

__global__ void __launch_bounds__(512, 2) attn_kernel() {
    extern __shared__ float sm[];
    float* q_s = sm;                  // 32 x QS (Q during QK; scores/P after)
    float* Ssm = sm;                  // alias
    float* kv = sm + 32 * QS;         // 256 x KVS
    float* outp = kv + 256 * KVS;     // 4 x (32 x KVS)
    int* mky = (int*)(outp + 4 * 32 * KVS);
    int* mkx = mky + 256;

    int t = threadIdx.x;
    int warp = t >> 5;
    int blk = blockIdx.x;
    int b = blk >> 7;
    int tile = blk & 127;
    int qy0 = (tile >> 4) * 8, qx0 = (tile & 15) * 4;
    int uy0 = qy0 - 5 < 0 ? 0 : qy0 - 5;
    int uy1 = qy0 + 12 > 63 ? 63 : qy0 + 12;
    int ux0 = qx0 - 5 < 0 ? 0 : qx0 - 5;
    int ux1 = qx0 + 8 > 63 ? 63 : qx0 + 8;
    int uw = ux1 - ux0 + 1;
    int M = (uy1 - uy0 + 1) * uw;

    if (t < 256) {
        int ry = t / uw;
        mky[t] = uy0 + ry;
        mkx[t] = ux0 + (t - ry * uw);
    }
    __syncthreads();

    // stage Q (32 x 256 into 32 x QS rows)
    for (int i = t; i < 2048; i += 512) {
        int qi = i >> 6, f4 = (i & 63) << 2;
        int qy = qy0 + (qi >> 2), qx = qx0 + (qi & 3);
        cp16(q_s + qi * QS + f4, g_q + ((((b << 12) + (qy << 6) + qx) << 8) + f4));
    }
    cp_commit();

    // ---- QK via wmma ----
    wmma::fragment<wmma::accumulator, 16, 16, 8, float> sacc[2];
    wmma::fill_fragment(sacc[0], 0.f);
    wmma::fill_fragment(sacc[1], 0.f);
    int mt = warp & 1, nt0 = warp >> 1;

    for (int ch = 0; ch < 8; ch++) {
        __syncthreads();
        for (int i = t; i < 2048; i += 512) {
            int r = i >> 3, f4 = (i & 7) << 2;
            if (r < M) {
                int m = (mky[r] << 6) + mkx[r];
                cp16(kv + r * KVS + f4, g_k + ((((b << 12) + m) << 8) + (ch << 5) + f4));
            } else {
                *(float4*)(kv + r * KVS + f4) = make_float4(0.f, 0.f, 0.f, 0.f);
            }
        }
        cp_commit();
        cp_wait<0>();
        __syncthreads();
#pragma unroll
        for (int s = 0; s < 4; s++) {
            wmma::fragment<wmma::matrix_a, 16, 16, 8, wmma::precision::tf32, wmma::row_major> af;
            wmma::fragment<wmma::matrix_b, 16, 16, 8, wmma::precision::tf32, wmma::col_major> bf0, bf1;
            wmma::load_matrix_sync(af, &q_s[mt * 16 * QS + (ch << 5) + s * 8], QS);
#pragma unroll
            for (int e = 0; e < af.num_elements; e++) af.x[e] = wmma::__float_to_tf32(af.x[e]);
            wmma::load_matrix_sync(bf0, &kv[nt0 * 16 * KVS + s * 8], KVS);
            wmma::load_matrix_sync(bf1, &kv[(nt0 + 8) * 16 * KVS + s * 8], KVS);
#pragma unroll
            for (int e = 0; e < bf0.num_elements; e++) {
                bf0.x[e] = wmma::__float_to_tf32(bf0.x[e]);
                bf1.x[e] = wmma::__float_to_tf32(bf1.x[e]);
            }
            wmma::mma_sync(sacc[0], af, bf0, sacc[0]);
            wmma::mma_sync(sacc[1], af, bf1, sacc[1]);
        }
    }
    __syncthreads();
    wmma::store_matrix_sync(&Ssm[mt * 16 * QS + nt0 * 16], sacc[0], QS, wmma::mem_row_major);
    wmma::store_matrix_sync(&Ssm[mt * 16 * QS + (nt0 + 8) * 16], sacc[1], QS, wmma::mem_row_major);
    __syncthreads();

    // ---- mask + softmax (fp32 exact) ----
    {
        int qi = t >> 4, l = t & 15;
        int qy = qy0 + (qi >> 2), qx = qx0 + (qi & 3);
        float v[16];
        float mx = -1e30f;
#pragma unroll
        for (int k = 0; k < 16; k++) {
            int s = l + 16 * k;
            float raw = Ssm[qi * QS + s];
            int dy = mky[s] - qy; if (dy < 0) dy = -dy;
            int dx = mkx[s] - qx; if (dx < 0) dx = -dx;
            v[k] = (s < M && dy <= 5 && dx <= 5) ? raw * 0.0625f : -1e30f;
            mx = fmaxf(mx, v[k]);
        }
#pragma unroll
        for (int d = 8; d; d >>= 1) mx = fmaxf(mx, __shfl_xor_sync(~0u, mx, d));
        float s = 0.f;
#pragma unroll
        for (int k = 0; k < 16; k++) { v[k] = expf(v[k] - mx); s += v[k]; }
#pragma unroll
        for (int d = 8; d; d >>= 1) s += __shfl_xor_sync(~0u, s, d);
        float inv = 1.f / s;
#pragma unroll
        for (int k = 0; k < 16; k++) Ssm[qi * QS + l + 16 * k] = v[k] * inv;
    }

    // ---- AV via wmma; V staged from g_v (row-major, cp.async) ----
    int kq = warp >> 2;
    int mtv = (warp >> 1) & 1;
    int ntc = warp & 1;

    for (int ch = 0; ch < 8; ch++) {
        __syncthreads();
        for (int i = t; i < 2048; i += 512) {
            int r = i >> 3, f4 = (i & 7) << 2;
            if (r < M) {
                int m = (mky[r] << 6) + mkx[r];
                cp16(kv + r * KVS + f4, g_v + ((((size_t)(b << 12) + m) << 8) + (ch << 5) + f4));
            } else {
                *(float4*)(kv + r * KVS + f4) = make_float4(0.f, 0.f, 0.f, 0.f);
            }
        }
        cp_commit();
        cp_wait<0>();
        __syncthreads();

        wmma::fragment<wmma::accumulator, 16, 16, 8, float> oacc;
        wmma::fill_fragment(oacc, 0.f);
#pragma unroll
        for (int s = 0; s < 8; s++) {
            wmma::fragment<wmma::matrix_a, 16, 16, 8, wmma::precision::tf32, wmma::row_major> pf;
            wmma::fragment<wmma::matrix_b, 16, 16, 8, wmma::precision::tf32, wmma::row_major> vf;
            wmma::load_matrix_sync(pf, &Ssm[mtv * 16 * QS + kq * 64 + s * 8], QS);
            wmma::load_matrix_sync(vf, &kv[(kq * 64 + s * 8) * KVS + ntc * 16], KVS);
#pragma unroll
            for (int e = 0; e < pf.num_elements; e++) pf.x[e] = wmma::__float_to_tf32(pf.x[e]);
#pragma unroll
            for (int e = 0; e < vf.num_elements; e++) vf.x[e] = wmma::__float_to_tf32(vf.x[e]);
            wmma::mma_sync(oacc, pf, vf, oacc);
        }
        wmma::store_matrix_sync(&outp[kq * 32 * KVS + mtv * 16 * KVS + ntc * 16], oacc, KVS,
                                wmma::mem_row_major);
        __syncthreads();

        // reduce 4 k-partials; threads iterate q fastest for contiguous pixel runs
        for (int i = t; i < 1024; i += 512) {
            int q = i & 31, c = i >> 5;
            float vs = outp[q * KVS + c] + outp[32 * KVS + q * KVS + c] +
                       outp[64 * KVS + q * KVS + c] + outp[96 * KVS + q * KVS + c];
            int pix = ((qy0 + (q >> 2)) << 6) + qx0 + (q & 3);
            g_aoT[(((size_t)(b << 8) + (ch << 5) + c) << 12) + pix] = vs;
        }
    }
}

// ---------------- launch ----------------
extern "C" void kernel_launch(void* const* d_in, const int* in_sizes, int n_in,
                              void* d_out, int out_size) {
    const float* ef  = (const float*)d_in[0];
    const float* sem = (const float*)d_in[1];
    const float* ff  = (const float*)d_in[2];
    const float* wa  = (const float*)d_in[3];
    const float* ba  = (const float*)d_in[4];
    const float* wfa = (const float*)d_in[5];
    const float* bfa = (const float*)d_in[6];
    const float* wq  = (const float*)d_in[7];
    const float* bq  = (const float*)d_in[8];
    const float* wk  = (const float*)d_in[9];
    const float* bk  = (const float*)d_in[10];
    const float* wfu = (const float*)d_in[11];
    const float* bfu = (const float*)d_in[12];
    float* out = (float*)d_out;

    cudaFuncSetAttribute(attn_kernel, cudaFuncAttributeMaxDynamicSharedMemorySize, ATTN_SMEM);

    wprep_kernel<<<608, 256>>>(wq, wk, wfu, wa, wfa);                        // 0
    gemm_tc_kernel<<<dim3(8, 1, 4), 256>>>(3, ba, nullptr, ef, ff);          // 1 edge conv
    gemm_tc_kernel<<<dim3(8, 1, 4), 256>>>(4, bfa, nullptr, ef, ff);         // 2 fused conv
    prep_kernel<<<256, 256>>>(sem);                                          // 3 <- profiled
    density_kernel<<<4, 1024>>>();                                           // 4
    scale_kernel<<<2048, 256>>>(sem);                                        // 5
    vbuild_kernel<<<dim3(128, 8, 4), 256>>>(sem);                            // 6
    gemm_tc_kernel<<<dim3(32, 2, 4), 256>>>(0, bq, nullptr, ef, ff);         // 7 Q
    gemm_tc_kernel<<<dim3(32, 2, 4), 256>>>(1, bk, nullptr, ef, ff);         // 8 K
    attn_kernel<<<512, 512, ATTN_SMEM>>>();                                  // 9
    gemm_tc_kernel<<<dim3(32, 1, 4), 256>>>(2, bfu, out, ef, ff);            // 10 F
}